// round 16
// baseline (speedup 1.0000x reference)
#include <cuda_runtime.h>
#include <math.h>
#include <stdint.h>

#define S_LEN 8192
#define LCC   16
#define DW    256
#define DC    64
#define HC    128
#define HH    512
#define CVV   128
#define T_TAGS 64
#define H2    256
#define KIN   384      /* HC + DW */
#define NBC   16       /* CTAs per direction (nonportable cluster of 16) */
#define RT2   128      /* 4 warps per CTA; each warp owns 4 h-units */

/* ------------------- scratch (device globals; no allocation) ------------- */
__device__ float g_XW[CVV * 4 * HC];                   /* per-char input proj (permuted) */
__device__ float g_Hc2[2][S_LEN * HC];                 /* double-buffered char h */
__device__ float g_Cc[S_LEN * HC];
__device__ float g_charfeat[S_LEN * HC];
__device__ float g_Gf[(size_t)S_LEN * 4 * H2];
__device__ float g_Gb[(size_t)S_LEN * 4 * H2];
__device__ float g_lstm_out[S_LEN * HH];
__device__ float g_logits[S_LEN * T_TAGS];

/* fast gates: hardware MUFU tanh (sm_75+); sigmoid via tanh identity */
__device__ __forceinline__ float tanh_fast(float x) {
    float y;
    asm("tanh.approx.f32 %0, %1;" : "=f"(y) : "f"(x));
    return y;
}
__device__ __forceinline__ float sig_fast(float x) {
    return fmaf(tanh_fast(0.5f * x), 0.5f, 0.5f);
}

/* ---- PTX helpers ---- */
__device__ __forceinline__ uint32_t smem_u32(const void* p) {
    uint32_t a;
    asm("{ .reg .u64 t; cvta.to.shared.u64 t, %1; cvt.u32.u64 %0, t; }" : "=r"(a) : "l"(p));
    return a;
}
__device__ __forceinline__ uint32_t mapa_rank(uint32_t addr, uint32_t rank) {
    uint32_t r;
    asm("mapa.shared::cluster.u32 %0, %1, %2;" : "=r"(r) : "r"(addr), "r"(rank));
    return r;
}
__device__ __forceinline__ void mbar_wait_acq(uint32_t mbar, uint32_t parity) {
    uint32_t done;
    asm volatile(
        "{\n\t.reg .pred p;\n\t"
        "mbarrier.try_wait.parity.acquire.cluster.shared::cta.b64 p, [%1], %2;\n\t"
        "selp.b32 %0, 1, 0, p;\n\t}"
        : "=r"(done) : "r"(mbar), "r"(parity) : "memory");
    while (!done) {
        asm volatile(
            "{\n\t.reg .pred p;\n\t"
            "mbarrier.try_wait.parity.acquire.cluster.shared::cta.b64 p, [%1], %2, 0x989680;\n\t"
            "selp.b32 %0, 1, 0, p;\n\t}"
            : "=r"(done) : "r"(mbar), "r"(parity) : "memory");
    }
}
__device__ __forceinline__ void mbar_arm(uint32_t mbar, uint32_t tx) {
    asm volatile("mbarrier.arrive.expect_tx.shared::cta.b64 _, [%0], %1;"
                 :: "r"(mbar), "r"(tx) : "memory");
}
__device__ __forceinline__ void st_async_v2b64(uint32_t raddr, unsigned long long v0,
                                               unsigned long long v1, uint32_t rmbar) {
    asm volatile(
        "st.async.shared::cluster.mbarrier::complete_tx::bytes.v2.b64 [%0], {%1, %2}, [%3];"
        :: "r"(raddr), "l"(v0), "l"(v1), "r"(rmbar) : "memory");
}
#define FMA2(acc, a, b) asm("fma.rn.f32x2 %0, %1, %2, %0;" : "+l"(acc) : "l"(a), "l"(b))
#define UNPACK2(lo, hi, v) asm("mov.b64 {%0,%1}, %2;" : "=f"(lo), "=f"(hi) : "l"(v))

/* ------------------- init: must run every launch (graph determinism) ----- */
__global__ void init_state() {
    int idx = blockIdx.x * blockDim.x + threadIdx.x;
    int stride = gridDim.x * blockDim.x;
    for (int i = idx; i < S_LEN * HC; i += stride) {
        g_Hc2[0][i] = 0.0f;
        g_Cc[i] = 0.0f;
    }
}

/* ------------------- per-char input projection table ----------------------
 * XW[c][n] = dot(char_emb[c], cWih[borig]) + cb[borig],
 * borig = (n&3)*HC + (n>>2) (gate-permuted so unit's {i,f,g,o} adjacent).  */
__global__ void build_xw(const float* __restrict__ ce,
                         const float* __restrict__ Wih,
                         const float* __restrict__ cb) {
    int idx = blockIdx.x * blockDim.x + threadIdx.x;
    if (idx >= CVV * 4 * HC) return;
    int c = idx >> 9;
    int n = idx & 511;
    int borig = (n & 3) * HC + (n >> 2);
    const float* w = Wih + (size_t)borig * DC;
    const float* e = ce + (size_t)c * DC;
    float s = cb[borig];
#pragma unroll
    for (int k = 0; k < DC; k++) s = fmaf(e[k], w[k], s);
    g_XW[idx] = s;
}

/* ---- 128x64 tile GEMM body: 256 thr, 8x4 microtile, scalar FFMA inner ----
 * Per kk: 3 LDS.128 feed 32 FMAs (vs 2 per 16 in the 64x64 tile) ->
 * 1.5x less LDS traffic per FLOP; A reads broadcast (2 addrs/warp).
 * Loader roles: ar=tid>>1 (A row), ak=(tid&1)*8 (two float4 per thread);
 *               br=tid>>2 (B row), bk=(tid&3)*4 (one float4).             */
#define GEMM_BODY128(LOADA0, LOADA1, LOADB, KDIM)                            \
    __shared__ __align__(16) float4 As4[16 * 32];                            \
    __shared__ __align__(16) float4 Bs4[16 * 16];                            \
    float* As = (float*)As4;                                                 \
    float* Bs = (float*)Bs4;                                                 \
    int ty = tid >> 4, tx = tid & 15;                                        \
    float acc[8][4];                                                         \
    _Pragma("unroll")                                                        \
    for (int i = 0; i < 8; i++)                                              \
        _Pragma("unroll")                                                    \
        for (int j = 0; j < 4; j++) acc[i][j] = 0.0f;                        \
    for (int k0 = 0; k0 < KDIM; k0 += 16) {                                  \
        float4 a0 = LOADA0;                                                  \
        float4 a1 = LOADA1;                                                  \
        float4 b = LOADB;                                                    \
        __syncthreads();                                                     \
        As[(ak + 0) * 128 + ar] = a0.x;                                      \
        As[(ak + 1) * 128 + ar] = a0.y;                                      \
        As[(ak + 2) * 128 + ar] = a0.z;                                      \
        As[(ak + 3) * 128 + ar] = a0.w;                                      \
        As[(ak + 4) * 128 + ar] = a1.x;                                      \
        As[(ak + 5) * 128 + ar] = a1.y;                                      \
        As[(ak + 6) * 128 + ar] = a1.z;                                      \
        As[(ak + 7) * 128 + ar] = a1.w;                                      \
        Bs[(bk + 0) * 64 + br] = b.x;                                        \
        Bs[(bk + 1) * 64 + br] = b.y;                                        \
        Bs[(bk + 2) * 64 + br] = b.z;                                        \
        Bs[(bk + 3) * 64 + br] = b.w;                                        \
        __syncthreads();                                                     \
        _Pragma("unroll")                                                    \
        for (int kk = 0; kk < 16; kk++) {                                    \
            float4 av0 = As4[kk * 32 + ty * 2];                              \
            float4 av1 = As4[kk * 32 + ty * 2 + 1];                          \
            float4 bv = Bs4[kk * 16 + tx];                                   \
            float a_[8] = {av0.x, av0.y, av0.z, av0.w,                       \
                           av1.x, av1.y, av1.z, av1.w};                      \
            _Pragma("unroll")                                                \
            for (int r = 0; r < 8; r++) {                                    \
                acc[r][0] += a_[r] * bv.x;                                   \
                acc[r][1] += a_[r] * bv.y;                                   \
                acc[r][2] += a_[r] * bv.z;                                   \
                acc[r][3] += a_[r] * bv.w;                                   \
            }                                                                \
        }                                                                    \
    }

/* ------------------- generic fp32 GEMM (logits) --------------------------- */
__global__ void __launch_bounds__(256) gemm_tn(
    const float* __restrict__ A, int lda,
    const float* __restrict__ B,
    const float* __restrict__ bias,
    float* __restrict__ C, int M, int N, int KDIM)
{
    int tid = threadIdx.x;
    int m0 = blockIdx.y * 128, n0 = blockIdx.x * 64;
    int ar = tid >> 1, ak = (tid & 1) * 8;
    int br = tid >> 2, bk = (tid & 3) * 4;
    const float* Ap = A + (size_t)(m0 + ar) * lda;
    const float* Bp = B + (size_t)(n0 + br) * KDIM;

    GEMM_BODY128((*(const float4*)(Ap + k0 + ak)),
                 (*(const float4*)(Ap + k0 + ak + 4)),
                 (*(const float4*)(Bp + k0 + bk)), KDIM)

#pragma unroll
    for (int i = 0; i < 8; i++) {
        int m = m0 + ty * 8 + i;
        int n = n0 + tx * 4;
        float4 o;
        o.x = acc[i][0] + bias[n + 0];
        o.y = acc[i][1] + bias[n + 1];
        o.z = acc[i][2] + bias[n + 2];
        o.w = acc[i][3] + bias[n + 3];
        *(float4*)(C + (size_t)m * N + n) = o;
    }
}

/* ------------------- fused char LSTM step (128-row tile) ------------------ */
__global__ void __launch_bounds__(256) char_step_fused(
    const float* __restrict__ HcR, const float* __restrict__ Whh,
    const int* __restrict__ charsets, float* __restrict__ Cc,
    float* __restrict__ HcW, float* __restrict__ charfeat,
    const int* __restrict__ lengths, int t)
{
    int tid = threadIdx.x;
    int m0 = blockIdx.y * 128, n0 = blockIdx.x * 64;
    int ar = tid >> 1, ak = (tid & 1) * 8;
    int br = tid >> 2, bk = (tid & 3) * 4;

    const float* Ap = HcR + (size_t)(m0 + ar) * HC;
    int brow = n0 + br;
    int borig = (brow & 3) * HC + (brow >> 2);
    const float* Bp = Whh + (size_t)borig * HC;

    GEMM_BODY128((*(const float4*)(Ap + k0 + ak)),
                 (*(const float4*)(Ap + k0 + ak + 4)),
                 (*(const float4*)(Bp + k0 + bk)), HC)

    int unit = (n0 >> 2) + tx;
#pragma unroll
    for (int i = 0; i < 8; i++) {
        int m = m0 + ty * 8 + i;
        int cidx = charsets[m * LCC + t];
        float4 x = *(const float4*)(g_XW + (size_t)cidx * (4 * HC) + unit * 4);
        float gi = acc[i][0] + x.x;
        float gf = acc[i][1] + x.y;
        float gg = acc[i][2] + x.z;
        float go = acc[i][3] + x.w;
        float c = Cc[m * HC + unit];
        c = sig_fast(gf) * c + sig_fast(gi) * tanh_fast(gg);
        float h = sig_fast(go) * tanh_fast(c);
        Cc[m * HC + unit] = c;
        HcW[m * HC + unit] = h;
        if (t == lengths[m] - 1) charfeat[m * HC + unit] = h;
    }
}

/* ------------------- projection GEMM with fused embeds (128-row tile) ----- */
__global__ void __launch_bounds__(256) gemm_emb(
    const int* __restrict__ sent,
    const float* __restrict__ cfeat,
    const float* __restrict__ wemb,
    const float* __restrict__ B,
    const float* __restrict__ bias,
    float* __restrict__ C, int M, int N, int rev)
{
    int tid = threadIdx.x;
    int m0 = blockIdx.y * 128, n0 = blockIdx.x * 64;
    int ar = tid >> 1, ak = (tid & 1) * 8;
    int br = tid >> 2, bk = (tid & 3) * 4;

    int mg = m0 + ar;
    int arow = rev ? (M - 1 - mg) : mg;
    int sidx = sent[arow];
    const float* cf = cfeat + (size_t)arow * HC;
    const float* we = wemb + (size_t)sidx * DW - HC;   /* index by col directly */
    const float* Bp = B + (size_t)(n0 + br) * KIN;

    GEMM_BODY128(((k0 + ak < HC) ? *(const float4*)(cf + k0 + ak)
                                 : *(const float4*)(we + k0 + ak)),
                 ((k0 + ak + 4 < HC) ? *(const float4*)(cf + k0 + ak + 4)
                                     : *(const float4*)(we + k0 + ak + 4)),
                 (*(const float4*)(Bp + k0 + bk)), KIN)

#pragma unroll
    for (int i = 0; i < 8; i++) {
        int m = m0 + ty * 8 + i;
        int n = n0 + tx * 4;
        float4 o;
        o.x = acc[i][0] + bias[n + 0];
        o.y = acc[i][1] + bias[n + 1];
        o.z = acc[i][2] + bias[n + 2];
        o.w = acc[i][3] + bias[n + 3];
        *(float4*)(C + (size_t)m * N + n) = o;
    }
}

/* ------------------- barrier-free cluster recurrence (R13 exact) ----------
 * 2 nonportable clusters of 16 CTAs (one per direction), 128 threads =
 * 4 warps/CTA. Each WARP owns 4 h-units end-to-end. Lanes 0-3 each push
 * ONE 16-B st.async.v2.b64 to 4 of the 16 peer CTAs (parallel push).
 * Receiver: 64 tx events x 16 B per step, two alternating expect_tx(1024)
 * mbarriers re-armed by tid0 after wait. No syncthreads in the loop.      */
__global__ void __launch_bounds__(RT2, 1) __cluster_dims__(NBC, 1, 1)
recurrent_cluster(const float* __restrict__ WhhF, const float* __restrict__ WhhB)
{
    __shared__ __align__(16) float s_h[2][H2];
    __shared__ __align__(8) unsigned long long s_mbar[2];

    int tid = threadIdx.x;
    int wid = tid >> 5;
    int lane = tid & 31;
    int d = blockIdx.x >> 4;       /* cluster id = direction        */
    int b = blockIdx.x & 15;       /* rank within cluster           */
    const float* Whh = d ? WhhB : WhhF;
    const float* G = d ? g_Gb : g_Gf;

    int seg = lane & 1;            /* k half 0..1                    */
    int r_l = lane >> 1;           /* 0..15: ul = r_l>>2, gk = r_l&3 */
    int ul = r_l >> 2;
    int gk = r_l & 3;
    int u = b * 16 + wid * 4 + ul; /* global h-unit of this lane     */
    int row = gk * H2 + u;         /* gate row                       */

    /* 128 weights per lane, packed f32x2; k interleaved by float4(seg) */
    ulonglong2 w[32];
    const float* wrow = Whh + (size_t)row * H2;
#pragma unroll
    for (int jj = 0; jj < 32; jj++)
        w[jj] = *reinterpret_cast<const ulonglong2*>(wrow + (jj * 2 + seg) * 4);

    for (int i = tid; i < H2; i += RT2) { s_h[0][i] = 0.0f; s_h[1][i] = 0.0f; }

    uint32_t mb0 = smem_u32(&s_mbar[0]);
    uint32_t mb1 = smem_u32(&s_mbar[1]);
    if (tid == 0) {
        asm volatile("mbarrier.init.shared.b64 [%0], %1;" :: "r"(mb0), "r"(1) : "memory");
        asm volatile("mbarrier.init.shared.b64 [%0], %1;" :: "r"(mb1), "r"(1) : "memory");
        mbar_arm(mb0, 1024);   /* receives wave 1 */
        mbar_arm(mb1, 1024);   /* receives wave 0 */
        asm volatile("fence.mbarrier_init.release.cluster;" ::: "memory");
    }

    /* lanes 0..3 push to peers lane*4 .. lane*4+3 */
    uint32_t rh0[4], rh1[4], rm0[4], rm1[4];
    if (lane < 4) {
        uint32_t off = (uint32_t)(b * 16 + wid * 4) * 4u;
        uint32_t h0 = smem_u32(&s_h[0][0]) + off;
        uint32_t h1 = smem_u32(&s_h[1][0]) + off;
#pragma unroll
        for (int p = 0; p < 4; p++) {
            uint32_t peer = (uint32_t)(lane * 4 + p);
            rh0[p] = mapa_rank(h0, peer);
            rh1[p] = mapa_rank(h1, peer);
            rm0[p] = mapa_rank(mb0, peer);
            rm1[p] = mapa_rank(mb1, peer);
        }
    }

    __syncthreads();
    asm volatile("barrier.cluster.arrive.aligned;" ::: "memory");
    asm volatile("barrier.cluster.wait.aligned;" ::: "memory");

    uint32_t ph0 = 0, ph1 = 0;
    float c = 0.0f;
    float gin = 0.0f;
    if (seg == 0) gin = G[row];    /* prefetch t=0 */

    for (int t = 0; t < S_LEN; t++) {
        int idx = t & 1;
        if (t > 0) {
            uint32_t mb = idx ? mb1 : mb0;
            uint32_t ph = idx ? ph1 : ph0;
            mbar_wait_acq(mb, ph);
            if (idx) ph1 ^= 1; else ph0 ^= 1;
            if (tid == 0) mbar_arm(mb, 1024);   /* re-arm for wave t+2 */
        }

        const float* hb = s_h[idx];
        unsigned long long acc0 = 0ull, acc1 = 0ull;
#pragma unroll
        for (int jj = 0; jj < 32; jj++) {
            ulonglong2 hv = *reinterpret_cast<const ulonglong2*>(hb + (jj * 2 + seg) * 4);
            FMA2(acc0, w[jj].x, hv.x);
            FMA2(acc1, w[jj].y, hv.y);
        }
        float a0, a1, a2, a3;
        UNPACK2(a0, a1, acc0);
        UNPACK2(a2, a3, acc1);
        float acc = (a0 + a1) + (a2 + a3);
        acc += __shfl_xor_sync(0xffffffffu, acc, 1);   /* reduce k halves */
        if (seg == 0) acc += gin;                      /* +input proj     */

        /* gather this lane's unit gates (sources: even lanes) */
        int base = lane & 24;                          /* (lane>>3)*8     */
        float gi = __shfl_sync(0xffffffffu, acc, base + 0);
        float gf = __shfl_sync(0xffffffffu, acc, base + 2);
        float gg = __shfl_sync(0xffffffffu, acc, base + 4);
        float go = __shfl_sync(0xffffffffu, acc, base + 6);

        c = sig_fast(gf) * c + sig_fast(gi) * tanh_fast(gg);
        float h = sig_fast(go) * tanh_fast(c);

        if (seg == 0 && t + 1 < S_LEN)
            gin = G[(size_t)(t + 1) * (4 * H2) + row]; /* prefetch next   */

        if ((lane & 7) == 0) {                 /* lanes 0,8,16,24: 4 units */
            int outrow = d ? (S_LEN - 1 - t) : t;
            g_lstm_out[(size_t)outrow * HH + d * H2 + u] = h;
        }
        /* broadcast warp's 4 h values; lanes 0-3 push 4 peers each */
        float hB = __shfl_sync(0xffffffffu, h, 8);
        float hC = __shfl_sync(0xffffffffu, h, 16);
        float hD = __shfl_sync(0xffffffffu, h, 24);
        float hA = __shfl_sync(0xffffffffu, h, 0);

        if (lane < 4 && t + 1 < S_LEN) {
            unsigned long long p0, p1;
            asm("mov.b64 %0, {%1,%2};" : "=l"(p0) : "f"(hA), "f"(hB));
            asm("mov.b64 %0, {%1,%2};" : "=l"(p1) : "f"(hC), "f"(hD));
            if (idx) {          /* dst buffer 0, mbar 0 */
#pragma unroll
                for (int p = 0; p < 4; p++) st_async_v2b64(rh0[p], p0, p1, rm0[p]);
            } else {            /* dst buffer 1, mbar 1 */
#pragma unroll
                for (int p = 0; p < 4; p++) st_async_v2b64(rh1[p], p0, p1, rm1[p]);
            }
        }
    }

    asm volatile("barrier.cluster.arrive.aligned;" ::: "memory");
    asm volatile("barrier.cluster.wait.aligned;" ::: "memory");
}

/* ------------------- log_softmax over 64 tags (one warp per word) --------- */
__global__ void logsoftmax_kernel(float* __restrict__ out) {
    int gt = blockIdx.x * blockDim.x + threadIdx.x;
    int warp = gt >> 5;
    int lane = gt & 31;
    if (warp >= S_LEN) return;
    const float* l = g_logits + (size_t)warp * T_TAGS;
    float a = l[lane], b = l[lane + 32];
    float m = fmaxf(a, b);
#pragma unroll
    for (int o = 16; o > 0; o >>= 1) m = fmaxf(m, __shfl_xor_sync(0xffffffffu, m, o));
    float s = expf(a - m) + expf(b - m);
#pragma unroll
    for (int o = 16; o > 0; o >>= 1) s += __shfl_xor_sync(0xffffffffu, s, o);
    float lse = m + logf(s);
    out[(size_t)warp * T_TAGS + lane] = a - lse;
    out[(size_t)warp * T_TAGS + lane + 32] = b - lse;
}

/* ------------------- launcher --------------------------------------------- */
extern "C" void kernel_launch(void* const* d_in, const int* in_sizes, int n_in,
                              void* d_out, int out_size) {
    const int*   sentence  = (const int*)d_in[0];
    const int*   charsets  = (const int*)d_in[1];
    const int*   lengths   = (const int*)d_in[2];
    const float* word_emb  = (const float*)d_in[3];
    const float* char_emb  = (const float*)d_in[4];
    const float* cWih      = (const float*)d_in[5];
    const float* cWhh      = (const float*)d_in[6];
    const float* cb        = (const float*)d_in[7];
    const float* fWih      = (const float*)d_in[8];
    const float* fWhh      = (const float*)d_in[9];
    const float* fb        = (const float*)d_in[10];
    const float* bWih      = (const float*)d_in[11];
    const float* bWhh      = (const float*)d_in[12];
    const float* bb        = (const float*)d_in[13];
    const float* outW      = (const float*)d_in[14];
    const float* outb      = (const float*)d_in[15];
    float* out = (float*)d_out;

    void *pHc2, *pCc, *pCf, *pGf, *pGb, *pLout, *pLog;
    cudaGetSymbolAddress(&pHc2, g_Hc2);
    cudaGetSymbolAddress(&pCc, g_Cc);
    cudaGetSymbolAddress(&pCf, g_charfeat);
    cudaGetSymbolAddress(&pGf, g_Gf);
    cudaGetSymbolAddress(&pGb, g_Gb);
    cudaGetSymbolAddress(&pLout, g_lstm_out);
    cudaGetSymbolAddress(&pLog, g_logits);

    float* Hc0 = (float*)pHc2;
    float* Hc1 = Hc0 + (size_t)S_LEN * HC;

    /* allow 16-CTA (nonportable) clusters for the recurrent kernel */
    cudaFuncSetAttribute(recurrent_cluster,
                         cudaFuncAttributeNonPortableClusterSizeAllowed, 1);

    /* reset per-launch state (graph-replay determinism) */
    init_state<<<2048, 256>>>();

    /* per-char input projection table: XW[128, 512] (gate-permuted + bias) */
    build_xw<<<(CVV * 4 * HC + 255) / 256, 256>>>(char_emb, cWih, cb);

    /* char LSTM: 16 fused GEMM+gate steps, double-buffered h, XW gather */
    for (int t = 0; t < LCC; t++) {
        const float* HcR = (t & 1) ? Hc1 : Hc0;
        float* HcW = (t & 1) ? Hc0 : Hc1;
        char_step_fused<<<dim3(8, S_LEN / 128), 256>>>(
            HcR, cWhh, charsets, (float*)pCc, HcW, (float*)pCf, lengths, t);
    }

    /* main input projections with fused embeds gather */
    gemm_emb<<<dim3(4 * H2 / 64, S_LEN / 128), 256>>>(
        sentence, (const float*)pCf, word_emb, fWih, fb, (float*)pGf,
        S_LEN, 4 * H2, 0);
    gemm_emb<<<dim3(4 * H2 / 64, S_LEN / 128), 256>>>(
        sentence, (const float*)pCf, word_emb, bWih, bb, (float*)pGb,
        S_LEN, 4 * H2, 1);

    /* sequential bidirectional recurrence: 2 nonportable clusters of 16 */
    recurrent_cluster<<<2 * NBC, RT2>>>(fWhh, bWhh);

    /* output projection + log_softmax */
    gemm_tn<<<dim3(T_TAGS / 64, S_LEN / 128), 256>>>(
        (const float*)pLout, HH, outW, outb, (float*)pLog,
        S_LEN, T_TAGS, HH);
    logsoftmax_kernel<<<(S_LEN * 32 + 255) / 256, 256>>>(out);
}

// round 17
// speedup vs baseline: 1.4292x; 1.4292x over previous
#include <cuda_runtime.h>
#include <math.h>
#include <stdint.h>

#define S_LEN 8192
#define LCC   16
#define DW    256
#define DC    64
#define HC    128
#define HH    512
#define CVV   128
#define T_TAGS 64
#define H2    256
#define KIN   384      /* HC + DW */
#define NBC   16       /* CTAs per direction (nonportable cluster of 16) */
#define RT2   128      /* 4 warps per CTA; each warp owns 4 h-units */

/* ------------------- scratch (device globals; no allocation) ------------- */
__device__ float g_XW[CVV * 4 * HC];                   /* per-char input proj (permuted) */
__device__ float g_Hc2[2][S_LEN * HC];                 /* double-buffered char h (sorted order) */
__device__ float g_Cc[S_LEN * HC];                     /* char c (sorted order) */
__device__ float g_charfeat[S_LEN * HC];               /* indexed by ORIGINAL word id */
__device__ float g_Gf[(size_t)S_LEN * 4 * H2];
__device__ float g_Gb[(size_t)S_LEN * 4 * H2];
__device__ float g_lstm_out[S_LEN * HH];
/* length-sort state */
__device__ int g_perm[S_LEN];
__device__ int g_cnt[16];
__device__ int g_cur[16];
__device__ int g_off[16];
__device__ int g_Nt[LCC];      /* N_t = #words with len >= t+1 */

/* fast gates: hardware MUFU tanh (sm_75+); sigmoid via tanh identity */
__device__ __forceinline__ float tanh_fast(float x) {
    float y;
    asm("tanh.approx.f32 %0, %1;" : "=f"(y) : "f"(x));
    return y;
}
__device__ __forceinline__ float sig_fast(float x) {
    return fmaf(tanh_fast(0.5f * x), 0.5f, 0.5f);
}

/* ---- PTX helpers ---- */
__device__ __forceinline__ uint32_t smem_u32(const void* p) {
    uint32_t a;
    asm("{ .reg .u64 t; cvta.to.shared.u64 t, %1; cvt.u32.u64 %0, t; }" : "=r"(a) : "l"(p));
    return a;
}
__device__ __forceinline__ uint32_t mapa_rank(uint32_t addr, uint32_t rank) {
    uint32_t r;
    asm("mapa.shared::cluster.u32 %0, %1, %2;" : "=r"(r) : "r"(addr), "r"(rank));
    return r;
}
__device__ __forceinline__ void mbar_wait_acq(uint32_t mbar, uint32_t parity) {
    uint32_t done;
    asm volatile(
        "{\n\t.reg .pred p;\n\t"
        "mbarrier.try_wait.parity.acquire.cluster.shared::cta.b64 p, [%1], %2;\n\t"
        "selp.b32 %0, 1, 0, p;\n\t}"
        : "=r"(done) : "r"(mbar), "r"(parity) : "memory");
    while (!done) {
        asm volatile(
            "{\n\t.reg .pred p;\n\t"
            "mbarrier.try_wait.parity.acquire.cluster.shared::cta.b64 p, [%1], %2, 0x989680;\n\t"
            "selp.b32 %0, 1, 0, p;\n\t}"
            : "=r"(done) : "r"(mbar), "r"(parity) : "memory");
    }
}
__device__ __forceinline__ void mbar_arm(uint32_t mbar, uint32_t tx) {
    asm volatile("mbarrier.arrive.expect_tx.shared::cta.b64 _, [%0], %1;"
                 :: "r"(mbar), "r"(tx) : "memory");
}
__device__ __forceinline__ void st_async_v2b64(uint32_t raddr, unsigned long long v0,
                                               unsigned long long v1, uint32_t rmbar) {
    asm volatile(
        "st.async.shared::cluster.mbarrier::complete_tx::bytes.v2.b64 [%0], {%1, %2}, [%3];"
        :: "r"(raddr), "l"(v0), "l"(v1), "r"(rmbar) : "memory");
}
#define FMA2(acc, a, b) asm("fma.rn.f32x2 %0, %1, %2, %0;" : "+l"(acc) : "l"(a), "l"(b))
#define UNPACK2(lo, hi, v) asm("mov.b64 {%0,%1}, %2;" : "=f"(lo), "=f"(hi) : "l"(v))

/* ------------------- init: must run every launch (graph determinism) ----- */
__global__ void init_state() {
    int idx = blockIdx.x * blockDim.x + threadIdx.x;
    int stride = gridDim.x * blockDim.x;
    if (idx < 16) { g_cnt[idx] = 0; g_cur[idx] = 0; }
    for (int i = idx; i < S_LEN * HC; i += stride) {
        g_Hc2[0][i] = 0.0f;
        g_Cc[i] = 0.0f;
    }
}

/* ------------------- length counting sort (descending) -------------------- */
__global__ void sort_hist(const int* __restrict__ lengths) {
    int w = blockIdx.x * blockDim.x + threadIdx.x;
    if (w < S_LEN) atomicAdd(&g_cnt[lengths[w] - 1], 1);
}
__global__ void sort_scan() {
    if (threadIdx.x == 0 && blockIdx.x == 0) {
        int off = 0;
        for (int li = 15; li >= 0; li--) {   /* descending length buckets */
            g_off[li] = off;
            off += g_cnt[li];
        }
        for (int t = 0; t < LCC; t++)        /* N_t = #len >= t+1 = off[t]+cnt[t] */
            g_Nt[t] = g_off[t] + g_cnt[t];
    }
}
__global__ void sort_scatter(const int* __restrict__ lengths) {
    int w = blockIdx.x * blockDim.x + threadIdx.x;
    if (w >= S_LEN) return;
    int li = lengths[w] - 1;
    int pos = g_off[li] + atomicAdd(&g_cur[li], 1);
    g_perm[pos] = w;
}

/* ------------------- per-char input projection table ----------------------
 * XW[c][n] = dot(char_emb[c], cWih[borig]) + cb[borig],
 * borig = (n&3)*HC + (n>>2) (gate-permuted so unit's {i,f,g,o} adjacent).  */
__global__ void build_xw(const float* __restrict__ ce,
                         const float* __restrict__ Wih,
                         const float* __restrict__ cb) {
    int idx = blockIdx.x * blockDim.x + threadIdx.x;
    if (idx >= CVV * 4 * HC) return;
    int c = idx >> 9;
    int n = idx & 511;
    int borig = (n & 3) * HC + (n >> 2);
    const float* w = Wih + (size_t)borig * DC;
    const float* e = ce + (size_t)c * DC;
    float s = cb[borig];
#pragma unroll
    for (int k = 0; k < DC; k++) s = fmaf(e[k], w[k], s);
    g_XW[idx] = s;
}

/* ------------------- fused char LSTM step (R13 64x64 body + sort skip) ----
 * Words stored in length-descending order; block skips if its rows are all
 * past their word length (m0 >= N_t). Epilogue gathers per ORIGINAL word
 * via perm[] for charsets/lengths/charfeat.                               */
__global__ void __launch_bounds__(256) char_step_fused(
    const float* __restrict__ HcR, const float* __restrict__ Whh,
    const int* __restrict__ charsets, float* __restrict__ Cc,
    float* __restrict__ HcW, float* __restrict__ charfeat,
    const int* __restrict__ lengths, int t)
{
    int m0 = blockIdx.y * 64, n0 = blockIdx.x * 64;
    if (m0 >= g_Nt[t]) return;            /* all rows here are finished */

    __shared__ float4 As4[16 * 16];
    __shared__ float4 Bs4[16 * 16];
    float* As = (float*)As4;
    float* Bs = (float*)Bs4;

    int tid = threadIdx.x;
    int lm = tid >> 2;
    int kq = tid & 3;

    const float* Ap = HcR + (size_t)(m0 + lm) * HC;
    int brow = n0 + lm;
    int borig = (brow & 3) * HC + (brow >> 2);
    const float* Bp = Whh + (size_t)borig * HC;

    int ty = tid >> 4, tx = tid & 15;
    float acc[4][4];
#pragma unroll
    for (int i = 0; i < 4; i++)
#pragma unroll
        for (int j = 0; j < 4; j++) acc[i][j] = 0.0f;

    for (int k0 = 0; k0 < HC; k0 += 16) {
        float4 a = *(const float4*)(Ap + k0 + kq * 4);
        float4 b = *(const float4*)(Bp + k0 + kq * 4);
        __syncthreads();
        As[(kq * 4 + 0) * 64 + lm] = a.x;
        As[(kq * 4 + 1) * 64 + lm] = a.y;
        As[(kq * 4 + 2) * 64 + lm] = a.z;
        As[(kq * 4 + 3) * 64 + lm] = a.w;
        Bs[(kq * 4 + 0) * 64 + lm] = b.x;
        Bs[(kq * 4 + 1) * 64 + lm] = b.y;
        Bs[(kq * 4 + 2) * 64 + lm] = b.z;
        Bs[(kq * 4 + 3) * 64 + lm] = b.w;
        __syncthreads();
#pragma unroll
        for (int kk = 0; kk < 16; kk++) {
            float4 av = As4[kk * 16 + ty];
            float4 bv = Bs4[kk * 16 + tx];
            acc[0][0] += av.x * bv.x; acc[0][1] += av.x * bv.y;
            acc[0][2] += av.x * bv.z; acc[0][3] += av.x * bv.w;
            acc[1][0] += av.y * bv.x; acc[1][1] += av.y * bv.y;
            acc[1][2] += av.y * bv.z; acc[1][3] += av.y * bv.w;
            acc[2][0] += av.z * bv.x; acc[2][1] += av.z * bv.y;
            acc[2][2] += av.z * bv.z; acc[2][3] += av.z * bv.w;
            acc[3][0] += av.w * bv.x; acc[3][1] += av.w * bv.y;
            acc[3][2] += av.w * bv.z; acc[3][3] += av.w * bv.w;
        }
    }

    int unit = (n0 >> 2) + tx;
#pragma unroll
    for (int i = 0; i < 4; i++) {
        int m = m0 + ty * 4 + i;
        int word = g_perm[m];
        int cidx = charsets[word * LCC + t];
        float4 x = *(const float4*)(g_XW + (size_t)cidx * (4 * HC) + unit * 4);
        float gi = acc[i][0] + x.x;
        float gf = acc[i][1] + x.y;
        float gg = acc[i][2] + x.z;
        float go = acc[i][3] + x.w;
        float c = Cc[m * HC + unit];
        c = sig_fast(gf) * c + sig_fast(gi) * tanh_fast(gg);
        float h = sig_fast(go) * tanh_fast(c);
        Cc[m * HC + unit] = c;
        HcW[m * HC + unit] = h;
        if (t == lengths[word] - 1) charfeat[word * HC + unit] = h;
    }
}

/* ------------------- projection GEMM with fused embeds (R13 exact) -------- */
__global__ void __launch_bounds__(256) gemm_emb(
    const int* __restrict__ sent,
    const float* __restrict__ cfeat,
    const float* __restrict__ wemb,
    const float* __restrict__ B,
    const float* __restrict__ bias,
    float* __restrict__ C, int M, int N, int rev)
{
    __shared__ float4 As4[16 * 16];
    __shared__ float4 Bs4[16 * 16];
    float* As = (float*)As4;
    float* Bs = (float*)Bs4;

    int tid = threadIdx.x;
    int m0 = blockIdx.y * 64, n0 = blockIdx.x * 64;
    int lm = tid >> 2;
    int kq = tid & 3;

    int mg = m0 + lm;
    int arow = rev ? (M - 1 - mg) : mg;
    int sidx = sent[arow];
    const float* cf = cfeat + (size_t)arow * HC;
    const float* we = wemb + (size_t)sidx * DW - HC;   /* index by col directly */
    const float* Bp = B + (size_t)(n0 + lm) * KIN;

    int ty = tid >> 4, tx = tid & 15;
    float acc[4][4];
#pragma unroll
    for (int i = 0; i < 4; i++)
#pragma unroll
        for (int j = 0; j < 4; j++) acc[i][j] = 0.0f;

    for (int k0 = 0; k0 < KIN; k0 += 16) {
        int col = k0 + kq * 4;
        float4 a = (col < HC) ? *(const float4*)(cf + col)
                              : *(const float4*)(we + col);
        float4 b = *(const float4*)(Bp + col);
        __syncthreads();
        As[(kq * 4 + 0) * 64 + lm] = a.x;
        As[(kq * 4 + 1) * 64 + lm] = a.y;
        As[(kq * 4 + 2) * 64 + lm] = a.z;
        As[(kq * 4 + 3) * 64 + lm] = a.w;
        Bs[(kq * 4 + 0) * 64 + lm] = b.x;
        Bs[(kq * 4 + 1) * 64 + lm] = b.y;
        Bs[(kq * 4 + 2) * 64 + lm] = b.z;
        Bs[(kq * 4 + 3) * 64 + lm] = b.w;
        __syncthreads();
#pragma unroll
        for (int kk = 0; kk < 16; kk++) {
            float4 av = As4[kk * 16 + ty];
            float4 bv = Bs4[kk * 16 + tx];
            acc[0][0] += av.x * bv.x; acc[0][1] += av.x * bv.y;
            acc[0][2] += av.x * bv.z; acc[0][3] += av.x * bv.w;
            acc[1][0] += av.y * bv.x; acc[1][1] += av.y * bv.y;
            acc[1][2] += av.y * bv.z; acc[1][3] += av.y * bv.w;
            acc[2][0] += av.z * bv.x; acc[2][1] += av.z * bv.y;
            acc[2][2] += av.z * bv.z; acc[2][3] += av.z * bv.w;
            acc[3][0] += av.w * bv.x; acc[3][1] += av.w * bv.y;
            acc[3][2] += av.w * bv.z; acc[3][3] += av.w * bv.w;
        }
    }
#pragma unroll
    for (int i = 0; i < 4; i++) {
        int m = m0 + ty * 4 + i;
        int n = n0 + tx * 4;
        float4 o;
        o.x = acc[i][0] + bias[n + 0];
        o.y = acc[i][1] + bias[n + 1];
        o.z = acc[i][2] + bias[n + 2];
        o.w = acc[i][3] + bias[n + 3];
        *(float4*)(C + (size_t)m * N + n) = o;
    }
}

/* ------------------- logits GEMM + fused log_softmax ----------------------
 * N = 64 = full tile width, so each thread row-group (fixed ty, tx=0..15)
 * holds a complete logits row: 16-lane xor-shfl reduction for max / sumexp,
 * then write log-softmax directly to out. K = 512.                        */
__global__ void __launch_bounds__(256) gemm_logits(
    const float* __restrict__ A,
    const float* __restrict__ B,
    const float* __restrict__ bias,
    float* __restrict__ out)
{
    __shared__ float4 As4[16 * 16];
    __shared__ float4 Bs4[16 * 16];
    float* As = (float*)As4;
    float* Bs = (float*)Bs4;

    int tid = threadIdx.x;
    int m0 = blockIdx.y * 64;
    int lm = tid >> 2;
    int kq = tid & 3;

    const float* Ap = A + (size_t)(m0 + lm) * HH;
    const float* Bp = B + (size_t)lm * HH;

    int ty = tid >> 4, tx = tid & 15;
    float acc[4][4];
#pragma unroll
    for (int i = 0; i < 4; i++)
#pragma unroll
        for (int j = 0; j < 4; j++) acc[i][j] = 0.0f;

    for (int k0 = 0; k0 < HH; k0 += 16) {
        float4 a = *(const float4*)(Ap + k0 + kq * 4);
        float4 b = *(const float4*)(Bp + k0 + kq * 4);
        __syncthreads();
        As[(kq * 4 + 0) * 64 + lm] = a.x;
        As[(kq * 4 + 1) * 64 + lm] = a.y;
        As[(kq * 4 + 2) * 64 + lm] = a.z;
        As[(kq * 4 + 3) * 64 + lm] = a.w;
        Bs[(kq * 4 + 0) * 64 + lm] = b.x;
        Bs[(kq * 4 + 1) * 64 + lm] = b.y;
        Bs[(kq * 4 + 2) * 64 + lm] = b.z;
        Bs[(kq * 4 + 3) * 64 + lm] = b.w;
        __syncthreads();
#pragma unroll
        for (int kk = 0; kk < 16; kk++) {
            float4 av = As4[kk * 16 + ty];
            float4 bv = Bs4[kk * 16 + tx];
            acc[0][0] += av.x * bv.x; acc[0][1] += av.x * bv.y;
            acc[0][2] += av.x * bv.z; acc[0][3] += av.x * bv.w;
            acc[1][0] += av.y * bv.x; acc[1][1] += av.y * bv.y;
            acc[1][2] += av.y * bv.z; acc[1][3] += av.y * bv.w;
            acc[2][0] += av.z * bv.x; acc[2][1] += av.z * bv.y;
            acc[2][2] += av.z * bv.z; acc[2][3] += av.z * bv.w;
            acc[3][0] += av.w * bv.x; acc[3][1] += av.w * bv.y;
            acc[3][2] += av.w * bv.z; acc[3][3] += av.w * bv.w;
        }
    }

    int n = tx * 4;
#pragma unroll
    for (int i = 0; i < 4; i++) {
        float l0 = acc[i][0] + bias[n + 0];
        float l1 = acc[i][1] + bias[n + 1];
        float l2 = acc[i][2] + bias[n + 2];
        float l3 = acc[i][3] + bias[n + 3];
        float mx = fmaxf(fmaxf(l0, l1), fmaxf(l2, l3));
#pragma unroll
        for (int o = 1; o < 16; o <<= 1)     /* xor<16 stays in ty group */
            mx = fmaxf(mx, __shfl_xor_sync(0xffffffffu, mx, o));
        float se = expf(l0 - mx) + expf(l1 - mx) + expf(l2 - mx) + expf(l3 - mx);
#pragma unroll
        for (int o = 1; o < 16; o <<= 1)
            se += __shfl_xor_sync(0xffffffffu, se, o);
        float lse = mx + logf(se);
        int m = m0 + ty * 4 + i;
        float4 o4;
        o4.x = l0 - lse; o4.y = l1 - lse; o4.z = l2 - lse; o4.w = l3 - lse;
        *(float4*)(out + (size_t)m * T_TAGS + n) = o4;
    }
}

/* ------------------- barrier-free cluster recurrence (R13 exact) ----------
 * 2 nonportable clusters of 16 CTAs (one per direction), 128 threads =
 * 4 warps/CTA. Each WARP owns 4 h-units end-to-end. Lanes 0-3 each push
 * ONE 16-B st.async.v2.b64 to 4 of the 16 peer CTAs (parallel push).
 * Receiver: 64 tx events x 16 B per step, two alternating expect_tx(1024)
 * mbarriers re-armed by tid0 after wait. No syncthreads in the loop.      */
__global__ void __launch_bounds__(RT2, 1) __cluster_dims__(NBC, 1, 1)
recurrent_cluster(const float* __restrict__ WhhF, const float* __restrict__ WhhB)
{
    __shared__ __align__(16) float s_h[2][H2];
    __shared__ __align__(8) unsigned long long s_mbar[2];

    int tid = threadIdx.x;
    int wid = tid >> 5;
    int lane = tid & 31;
    int d = blockIdx.x >> 4;       /* cluster id = direction        */
    int b = blockIdx.x & 15;       /* rank within cluster           */
    const float* Whh = d ? WhhB : WhhF;
    const float* G = d ? g_Gb : g_Gf;

    int seg = lane & 1;            /* k half 0..1                    */
    int r_l = lane >> 1;           /* 0..15: ul = r_l>>2, gk = r_l&3 */
    int ul = r_l >> 2;
    int gk = r_l & 3;
    int u = b * 16 + wid * 4 + ul; /* global h-unit of this lane     */
    int row = gk * H2 + u;         /* gate row                       */

    /* 128 weights per lane, packed f32x2; k interleaved by float4(seg) */
    ulonglong2 w[32];
    const float* wrow = Whh + (size_t)row * H2;
#pragma unroll
    for (int jj = 0; jj < 32; jj++)
        w[jj] = *reinterpret_cast<const ulonglong2*>(wrow + (jj * 2 + seg) * 4);

    for (int i = tid; i < H2; i += RT2) { s_h[0][i] = 0.0f; s_h[1][i] = 0.0f; }

    uint32_t mb0 = smem_u32(&s_mbar[0]);
    uint32_t mb1 = smem_u32(&s_mbar[1]);
    if (tid == 0) {
        asm volatile("mbarrier.init.shared.b64 [%0], %1;" :: "r"(mb0), "r"(1) : "memory");
        asm volatile("mbarrier.init.shared.b64 [%0], %1;" :: "r"(mb1), "r"(1) : "memory");
        mbar_arm(mb0, 1024);   /* receives wave 1 */
        mbar_arm(mb1, 1024);   /* receives wave 0 */
        asm volatile("fence.mbarrier_init.release.cluster;" ::: "memory");
    }

    /* lanes 0..3 push to peers lane*4 .. lane*4+3 */
    uint32_t rh0[4], rh1[4], rm0[4], rm1[4];
    if (lane < 4) {
        uint32_t off = (uint32_t)(b * 16 + wid * 4) * 4u;
        uint32_t h0 = smem_u32(&s_h[0][0]) + off;
        uint32_t h1 = smem_u32(&s_h[1][0]) + off;
#pragma unroll
        for (int p = 0; p < 4; p++) {
            uint32_t peer = (uint32_t)(lane * 4 + p);
            rh0[p] = mapa_rank(h0, peer);
            rh1[p] = mapa_rank(h1, peer);
            rm0[p] = mapa_rank(mb0, peer);
            rm1[p] = mapa_rank(mb1, peer);
        }
    }

    __syncthreads();
    asm volatile("barrier.cluster.arrive.aligned;" ::: "memory");
    asm volatile("barrier.cluster.wait.aligned;" ::: "memory");

    uint32_t ph0 = 0, ph1 = 0;
    float c = 0.0f;
    float gin = 0.0f;
    if (seg == 0) gin = G[row];    /* prefetch t=0 */

    for (int t = 0; t < S_LEN; t++) {
        int idx = t & 1;
        if (t > 0) {
            uint32_t mb = idx ? mb1 : mb0;
            uint32_t ph = idx ? ph1 : ph0;
            mbar_wait_acq(mb, ph);
            if (idx) ph1 ^= 1; else ph0 ^= 1;
            if (tid == 0) mbar_arm(mb, 1024);   /* re-arm for wave t+2 */
        }

        const float* hb = s_h[idx];
        unsigned long long acc0 = 0ull, acc1 = 0ull;
#pragma unroll
        for (int jj = 0; jj < 32; jj++) {
            ulonglong2 hv = *reinterpret_cast<const ulonglong2*>(hb + (jj * 2 + seg) * 4);
            FMA2(acc0, w[jj].x, hv.x);
            FMA2(acc1, w[jj].y, hv.y);
        }
        float a0, a1, a2, a3;
        UNPACK2(a0, a1, acc0);
        UNPACK2(a2, a3, acc1);
        float acc = (a0 + a1) + (a2 + a3);
        acc += __shfl_xor_sync(0xffffffffu, acc, 1);   /* reduce k halves */
        if (seg == 0) acc += gin;                      /* +input proj     */

        /* gather this lane's unit gates (sources: even lanes) */
        int base = lane & 24;                          /* (lane>>3)*8     */
        float gi = __shfl_sync(0xffffffffu, acc, base + 0);
        float gf = __shfl_sync(0xffffffffu, acc, base + 2);
        float gg = __shfl_sync(0xffffffffu, acc, base + 4);
        float go = __shfl_sync(0xffffffffu, acc, base + 6);

        c = sig_fast(gf) * c + sig_fast(gi) * tanh_fast(gg);
        float h = sig_fast(go) * tanh_fast(c);

        if (seg == 0 && t + 1 < S_LEN)
            gin = G[(size_t)(t + 1) * (4 * H2) + row]; /* prefetch next   */

        if ((lane & 7) == 0) {                 /* lanes 0,8,16,24: 4 units */
            int outrow = d ? (S_LEN - 1 - t) : t;
            g_lstm_out[(size_t)outrow * HH + d * H2 + u] = h;
        }
        /* broadcast warp's 4 h values; lanes 0-3 push 4 peers each */
        float hB = __shfl_sync(0xffffffffu, h, 8);
        float hC = __shfl_sync(0xffffffffu, h, 16);
        float hD = __shfl_sync(0xffffffffu, h, 24);
        float hA = __shfl_sync(0xffffffffu, h, 0);

        if (lane < 4 && t + 1 < S_LEN) {
            unsigned long long p0, p1;
            asm("mov.b64 %0, {%1,%2};" : "=l"(p0) : "f"(hA), "f"(hB));
            asm("mov.b64 %0, {%1,%2};" : "=l"(p1) : "f"(hC), "f"(hD));
            if (idx) {          /* dst buffer 0, mbar 0 */
#pragma unroll
                for (int p = 0; p < 4; p++) st_async_v2b64(rh0[p], p0, p1, rm0[p]);
            } else {            /* dst buffer 1, mbar 1 */
#pragma unroll
                for (int p = 0; p < 4; p++) st_async_v2b64(rh1[p], p0, p1, rm1[p]);
            }
        }
    }

    asm volatile("barrier.cluster.arrive.aligned;" ::: "memory");
    asm volatile("barrier.cluster.wait.aligned;" ::: "memory");
}

/* ------------------- launcher --------------------------------------------- */
extern "C" void kernel_launch(void* const* d_in, const int* in_sizes, int n_in,
                              void* d_out, int out_size) {
    const int*   sentence  = (const int*)d_in[0];
    const int*   charsets  = (const int*)d_in[1];
    const int*   lengths   = (const int*)d_in[2];
    const float* word_emb  = (const float*)d_in[3];
    const float* char_emb  = (const float*)d_in[4];
    const float* cWih      = (const float*)d_in[5];
    const float* cWhh      = (const float*)d_in[6];
    const float* cb        = (const float*)d_in[7];
    const float* fWih      = (const float*)d_in[8];
    const float* fWhh      = (const float*)d_in[9];
    const float* fb        = (const float*)d_in[10];
    const float* bWih      = (const float*)d_in[11];
    const float* bWhh      = (const float*)d_in[12];
    const float* bb        = (const float*)d_in[13];
    const float* outW      = (const float*)d_in[14];
    const float* outb      = (const float*)d_in[15];
    float* out = (float*)d_out;

    void *pHc2, *pCc, *pCf, *pGf, *pGb, *pLout;
    cudaGetSymbolAddress(&pHc2, g_Hc2);
    cudaGetSymbolAddress(&pCc, g_Cc);
    cudaGetSymbolAddress(&pCf, g_charfeat);
    cudaGetSymbolAddress(&pGf, g_Gf);
    cudaGetSymbolAddress(&pGb, g_Gb);
    cudaGetSymbolAddress(&pLout, g_lstm_out);

    float* Hc0 = (float*)pHc2;
    float* Hc1 = Hc0 + (size_t)S_LEN * HC;

    /* allow 16-CTA (nonportable) clusters for the recurrent kernel */
    cudaFuncSetAttribute(recurrent_cluster,
                         cudaFuncAttributeNonPortableClusterSizeAllowed, 1);

    /* reset per-launch state (graph-replay determinism) */
    init_state<<<2048, 256>>>();

    /* length counting sort (descending) + per-step active counts */
    sort_hist<<<S_LEN / 256, 256>>>(lengths);
    sort_scan<<<1, 32>>>();
    sort_scatter<<<S_LEN / 256, 256>>>(lengths);

    /* per-char input projection table: XW[128, 512] (gate-permuted + bias) */
    build_xw<<<(CVV * 4 * HC + 255) / 256, 256>>>(char_emb, cWih, cb);

    /* char LSTM: 16 fused GEMM+gate steps, sorted order + early exit */
    for (int t = 0; t < LCC; t++) {
        const float* HcR = (t & 1) ? Hc1 : Hc0;
        float* HcW = (t & 1) ? Hc0 : Hc1;
        char_step_fused<<<dim3(8, 128), 256>>>(
            HcR, cWhh, charsets, (float*)pCc, HcW, (float*)pCf, lengths, t);
    }

    /* main input projections with fused embeds gather */
    gemm_emb<<<dim3(4 * H2 / 64, S_LEN / 64), 256>>>(
        sentence, (const float*)pCf, word_emb, fWih, fb, (float*)pGf,
        S_LEN, 4 * H2, 0);
    gemm_emb<<<dim3(4 * H2 / 64, S_LEN / 64), 256>>>(
        sentence, (const float*)pCf, word_emb, bWih, bb, (float*)pGb,
        S_LEN, 4 * H2, 1);

    /* sequential bidirectional recurrence: 2 nonportable clusters of 16 */
    recurrent_cluster<<<2 * NBC, RT2>>>(fWhh, bWhh);

    /* output projection + fused log_softmax */
    gemm_logits<<<dim3(1, S_LEN / 64), 256>>>(
        (const float*)pLout, outW, outb, out);
}